// round 6
// baseline (speedup 1.0000x reference)
#include <cuda_runtime.h>
#include <math.h>

typedef unsigned long long u64;

#define NMAX 20000
#define EMAX 320000
#define N32  (NMAX * 32)

// f32x2 packed helpers
#define FMA2(d, a, b, c) asm("fma.rn.f32x2 %0, %1, %2, %3;" : "=l"(d) : "l"(a), "l"(b), "l"(c))
#define MUL2(d, a, b)    asm("mul.rn.f32x2 %0, %1, %2;" : "=l"(d) : "l"(a), "l"(b))
#define PACK2(d, lo, hi) asm("mov.b64 %0, {%1, %2};" : "=l"(d) : "f"(lo), "f"(hi))
#define UNPACK2(lo, hi, s) asm("mov.b64 {%0, %1}, %2;" : "=f"(lo), "=f"(hi) : "l"(s))

__device__ __forceinline__ float hadd2(u64 v) {
    float lo, hi; UNPACK2(lo, hi, v); return lo + hi;
}

// CSR build scratch
__device__ int g_deg[NMAX];
__device__ int g_off[NMAX + 1];
__device__ int g_cur[NMAX];
__device__ int g_edge[EMAX];

// transposed node features (plane-major for coalesced gather)
__device__ float g_n1T[3][N32];
__device__ float g_n2T[9][N32];

// aggregated per-node accumulators (plane-major)
__device__ float g_A0[N32];
__device__ float g_A1[3][N32];
__device__ float g_A2[9][N32];

// ---------------------------------------------------------------------------
__global__ void zero_deg_kernel(int N) {
    int i = blockIdx.x * blockDim.x + threadIdx.x;
    if (i < N) g_deg[i] = 0;
}

// fused histogram + feature transpose
__global__ void hist_transpose_kernel(const int* __restrict__ idx_i,
                                      const float* __restrict__ node1,
                                      const float* __restrict__ node2,
                                      int E, int NC) {
    int i = blockIdx.x * blockDim.x + threadIdx.x;
    if (i < E) atomicAdd(&g_deg[idx_i[i]], 1);
    if (i < NC) {
#pragma unroll
        for (int a = 0; a < 3; a++) g_n1T[a][i] = node1[(size_t)i * 3 + a];
#pragma unroll
        for (int k = 0; k < 9; k++) g_n2T[k][i] = node2[(size_t)i * 9 + k];
    }
}

__global__ void scan_kernel(int N, int E) {
    __shared__ int ssum[1024];
    int t = threadIdx.x;
    int chunk = (N + 1023) / 1024;
    int base = t * chunk;
    int s = 0;
    for (int k = 0; k < chunk; k++) {
        int idx = base + k;
        if (idx < N) s += g_deg[idx];
    }
    ssum[t] = s;
    __syncthreads();
    for (int off = 1; off < 1024; off <<= 1) {
        int v = (t >= off) ? ssum[t - off] : 0;
        __syncthreads();
        ssum[t] += v;
        __syncthreads();
    }
    int run = ssum[t] - s;
    for (int k = 0; k < chunk; k++) {
        int idx = base + k;
        if (idx < N) {
            int d = g_deg[idx];
            g_off[idx] = run;
            g_cur[idx] = run;
            run += d;
        }
    }
    if (t == 0) g_off[N] = E;
}

__global__ void scatter_kernel(const int* __restrict__ idx_i, int E) {
    int e = blockIdx.x * blockDim.x + threadIdx.x;
    if (e < E) {
        int p = atomicAdd(&g_cur[idx_i[e]], 1);
        g_edge[p] = e;
    }
}

// ---------------------------------------------------------------------------
// Edge aggregation: warp per node, lane = channel.
// Wrad pre-packed into 44 basis-pair f32x2 registers (packed once).
// rbf via 2-exp Gaussian ratio recurrence. One-edge-ahead gather pipeline.
// ---------------------------------------------------------------------------
__global__ __launch_bounds__(128, 3)
void edge_kernel(const float* __restrict__ node0,
                 const float* __restrict__ rij,
                 const float* __restrict__ Wrad,
                 const int* __restrict__ idx_j,
                 int N)
{
    int warp = threadIdx.x >> 5;
    int lane = threadIdx.x & 31;
    int n = blockIdx.x * 4 + warp;
    if (n >= N) return;

    // Wrad[p][b][lane], packed over basis pairs (done ONCE)
    u64 Wreg2[44];
#pragma unroll
    for (int p = 0; p < 11; p++)
#pragma unroll
        for (int i = 0; i < 4; i++) {
            float lo = Wrad[(p * 8 + 2 * i) * 32 + lane];
            float hi = Wrad[(p * 8 + 2 * i + 1) * 32 + lane];
            PACK2(Wreg2[p * 4 + i], lo, hi);
        }

    // Gaussian ratio constants: K[b] = exp(-9*(23+18b)/49)   (one-time, 7 MUFU)
    float Krec[7];
#pragma unroll
    for (int b = 0; b < 7; b++)
        Krec[b] = __expf(-(9.0f * (float)(23 + 18 * b)) * (1.0f / 49.0f));

    float A0 = 0.0f;
    float A1[3] = {0.0f, 0.0f, 0.0f};
    float A2[9] = {0.0f, 0.0f, 0.0f, 0.0f, 0.0f, 0.0f, 0.0f, 0.0f, 0.0f};

    int beg = g_off[n];
    int end = g_off[n + 1];

    for (int k0 = beg; k0 < end; k0 += 32) {
        int cnt = min(32, end - k0);
        int pos = k0 + lane;
        int eL = g_edge[(pos < end) ? pos : (end - 1)];
        int jL = idx_j[eL];

        // prime the pipeline: edge 0 features + rij
        int ec = __shfl_sync(0xffffffffu, eL, 0);
        int jc = __shfl_sync(0xffffffffu, jL, 0);
        int bc = jc * 32 + lane;
        float g0c = node0[bc];
        float g1c[3], g2c[9];
#pragma unroll
        for (int a = 0; a < 3; a++) g1c[a] = g_n1T[a][bc];
#pragma unroll
        for (int k = 0; k < 9; k++) g2c[k] = g_n2T[k][bc];
        float rxc = rij[3 * ec + 0], ryc = rij[3 * ec + 1], rzc = rij[3 * ec + 2];

        for (int kk = 0; kk < cnt; kk++) {
            // prefetch next edge (predicated; consumed next iteration)
            float g0n = 0.0f, g1n[3] = {0, 0, 0};
            float g2n[9] = {0, 0, 0, 0, 0, 0, 0, 0, 0};
            float rxn = 0.0f, ryn = 0.0f, rzn = 0.0f;
            if (kk + 1 < cnt) {
                int en = __shfl_sync(0xffffffffu, eL, kk + 1);
                int jn = __shfl_sync(0xffffffffu, jL, kk + 1);
                int bn = jn * 32 + lane;
                g0n = node0[bn];
#pragma unroll
                for (int a = 0; a < 3; a++) g1n[a] = g_n1T[a][bn];
#pragma unroll
                for (int k = 0; k < 9; k++) g2n[k] = g_n2T[k][bn];
                rxn = rij[3 * en + 0];
                ryn = rij[3 * en + 1];
                rzn = rij[3 * en + 2];
            }

            // ---- geometry (current edge) ----
            float dd = rxc * rxc + ryc * ryc + rzc * rzc + 1e-12f;
            float iv = rsqrtf(dd);
            float dist = dd * iv;
            float h0 = rxc * iv, h1 = ryc * iv, h2 = rzc * iv;

            float uu = fminf(dist * 0.2f, 1.0f);
            float fc = 0.5f * (__cosf(3.14159265358979323846f * uu) + 1.0f);

            // ---- rbf: 2 exp + ratio recurrence ----
            float dr = fminf(dist, 16.0f);
            float t0 = dr - 0.5f;
            float rb[8];
            rb[0] = __expf(-4.0f * t0 * t0) * fc;
            float ur = __expf((36.0f / 7.0f) * dr);
#pragma unroll
            for (int b = 0; b < 7; b++) rb[b + 1] = rb[b] * (ur * Krec[b]);

            u64 rb2[4];
#pragma unroll
            for (int i = 0; i < 4; i++) PACK2(rb2[i], rb[2 * i], rb[2 * i + 1]);

            // ---- per-path radial filters (44 FFMA2 + 11 hadd) ----
            float w[11];
#pragma unroll
            for (int p = 0; p < 11; p++) {
                u64 acc = 0ull;
#pragma unroll
                for (int i = 0; i < 4; i++) FMA2(acc, rb2[i], Wreg2[p * 4 + i], acc);
                w[p] = hadd2(acc);
            }

            // ---- moment contractions + messages ----
            float hh[3] = {h0, h1, h2};
            float d1 = g1c[0] * h0 + g1c[1] * h1 + g1c[2] * h2;
            float d2[3];
#pragma unroll
            for (int a = 0; a < 3; a++)
                d2[a] = g2c[a * 3 + 0] * h0 + g2c[a * 3 + 1] * h1 + g2c[a * 3 + 2] * h2;
            float q = d2[0] * h0 + d2[1] * h1 + d2[2] * h2;

            A0 += g0c * w[0] + d1 * w[4] + q * w[9];

            float s01 = g0c * w[1] + d1 * w[6];
#pragma unroll
            for (int a = 0; a < 3; a++)
                A1[a] += s01 * hh[a] + g1c[a] * w[3] + d2[a] * w[8];

            float gw2 = g0c * w[2];
#pragma unroll
            for (int a = 0; a < 3; a++) {
                float pre = gw2 * hh[a] + g1c[a] * w[5] + d2[a] * w[10];
#pragma unroll
                for (int b = 0; b < 3; b++)
                    A2[a * 3 + b] += pre * hh[b] + g2c[a * 3 + b] * w[7];
            }

            // rotate pipeline registers
            g0c = g0n;
#pragma unroll
            for (int a = 0; a < 3; a++) g1c[a] = g1n[a];
#pragma unroll
            for (int k = 0; k < 9; k++) g2c[k] = g2n[k];
            rxc = rxn; ryc = ryn; rzc = rzn;
        }
    }

    const float norm = 1.0f / 16.0f;
    int i0 = n * 32 + lane;
    g_A0[i0] = A0 * norm;
#pragma unroll
    for (int a = 0; a < 3; a++) g_A1[a][i0] = A1[a] * norm;
#pragma unroll
    for (int k = 0; k < 9; k++) g_A2[k][i0] = A2[k] * norm;
}

// ---------------------------------------------------------------------------
// Node kernel: warp per node; c-loop packed over channel pairs with f32x2.
// Weights pre-interleaved in shared as (c,c+1)-pairs -> single LDS.64 per use.
// ---------------------------------------------------------------------------
#define NWARPS 8

__global__ __launch_bounds__(256, 2)
void node_kernel(const float* __restrict__ node0,
                 const float* __restrict__ U,
                 const float* __restrict__ V,
                 const float* __restrict__ Wg,
                 float* __restrict__ out,
                 int N)
{
    extern __shared__ float sh[];
    float* sWm = sh;                           // 11*1024 paired
    float* sWg = sWm + 11264;                  // 3*1024 paired
    float* sX  = sWg + 3072;                   // NWARPS * 27 * 32
    float* sY  = sX + NWARPS * 27 * 32;        // NWARPS * 32

    for (int i = threadIdx.x; i < 11 * 1024; i += blockDim.x) {
        float v = (i < 3 * 1024) ? U[i] : V[i - 3 * 1024];
        int m = i >> 10, c = (i >> 5) & 31, d = i & 31;
        sWm[(m << 10) + ((c >> 1) << 6) + (d << 1) + (c & 1)] = v;
    }
    for (int i = threadIdx.x; i < 3 * 1024; i += blockDim.x) {
        int m = i >> 10, c = (i >> 5) & 31, d = i & 31;
        sWg[(m << 10) + ((c >> 1) << 6) + (d << 1) + (c & 1)] = Wg[i];
    }
    __syncthreads();

    int warp = threadIdx.x >> 5;
    int lane = threadIdx.x & 31;
    int n = blockIdx.x * NWARPS + warp;
    if (n >= N) return;

    int i0 = n * 32 + lane;
    float a0 = g_A0[i0];
    float a1[3];
#pragma unroll
    for (int a = 0; a < 3; a++) a1[a] = g_A1[a][i0];
    float a2[9];
#pragma unroll
    for (int k = 0; k < 9; k++) a2[k] = g_A2[k][i0];

    float s1 = a1[0] * a1[0] + a1[1] * a1[1] + a1[2] * a1[2];
    float s2 = 0.0f;
#pragma unroll
    for (int k = 0; k < 9; k++) s2 += a2[k] * a2[k];
    float t[3];
#pragma unroll
    for (int b = 0; b < 3; b++)
        t[b] = a1[0] * a2[0 * 3 + b] + a1[1] * a2[1 * 3 + b] + a1[2] * a2[2 * 3 + b];
    float r[9];
#pragma unroll
    for (int a = 0; a < 3; a++)
#pragma unroll
        for (int b = 0; b < 3; b++)
            r[a * 3 + b] = a2[a * 3 + 0] * a2[0 * 3 + b]
                         + a2[a * 3 + 1] * a2[1 * 3 + b]
                         + a2[a * 3 + 2] * a2[2 * 3 + b];

    float* Xs = sX + warp * 27 * 32;           // comp-major [27][32]
    Xs[0 * 32 + lane] = a0;
    Xs[1 * 32 + lane] = s1;
    Xs[2 * 32 + lane] = s2;
#pragma unroll
    for (int a = 0; a < 3; a++) { Xs[(3 + a) * 32 + lane] = a1[a]; Xs[(6 + a) * 32 + lane] = t[a]; }
#pragma unroll
    for (int k = 0; k < 9; k++) { Xs[(9 + k) * 32 + lane] = a2[k]; Xs[(18 + k) * 32 + lane] = r[k]; }
    __syncwarp();

    int d = lane;
    const u64* wm64 = (const u64*)sWm;         // idx: m*512 + cp*32 + d
    const u64* wg64 = (const u64*)sWg;

    u64 y0acc = 0ull;
    u64 y1acc[3] = {0ull, 0ull, 0ull};
    u64 y2acc[9] = {0ull, 0ull, 0ull, 0ull, 0ull, 0ull, 0ull, 0ull, 0ull};

#pragma unroll 2
    for (int cp = 0; cp < 16; cp++) {
        int c = cp * 2;
        int wb = cp * 32 + d;

        u64 xa0p = *(const u64*)(Xs + 0 * 32 + c);
        u64 xs1p = *(const u64*)(Xs + 1 * 32 + c);
        u64 xs2p = *(const u64*)(Xs + 2 * 32 + c);

        FMA2(y0acc, xa0p, wm64[0 * 512 + wb], y0acc);
        u64 xa0sq; MUL2(xa0sq, xa0p, xa0p);
        FMA2(y0acc, xa0sq, wm64[3 * 512 + wb], y0acc);
        FMA2(y0acc, xs1p, wm64[6 * 512 + wb], y0acc);
        FMA2(y0acc, xs2p, wm64[9 * 512 + wb], y0acc);

        u64 wU1 = wm64[1 * 512 + wb];
        u64 wV1 = wm64[4 * 512 + wb];
        u64 wV5 = wm64[8 * 512 + wb];
        u64 xa1p[3];
#pragma unroll
        for (int a = 0; a < 3; a++) {
            xa1p[a] = *(const u64*)(Xs + (3 + a) * 32 + c);
            u64 xtp = *(const u64*)(Xs + (6 + a) * 32 + c);
            FMA2(y1acc[a], xa1p[a], wU1, y1acc[a]);
            u64 p01; MUL2(p01, xa0p, xa1p[a]);
            FMA2(y1acc[a], p01, wV1, y1acc[a]);
            FMA2(y1acc[a], xtp, wV5, y1acc[a]);
        }

        u64 wU2 = wm64[2 * 512 + wb];
        u64 wV2 = wm64[5 * 512 + wb];
        u64 wV4 = wm64[7 * 512 + wb];
        u64 wV7 = wm64[10 * 512 + wb];
#pragma unroll
        for (int a = 0; a < 3; a++) {
#pragma unroll
            for (int b = 0; b < 3; b++) {
                int k = a * 3 + b;
                u64 xa2p = *(const u64*)(Xs + (9 + k) * 32 + c);
                u64 xrp  = *(const u64*)(Xs + (18 + k) * 32 + c);
                FMA2(y2acc[k], xa2p, wU2, y2acc[k]);
                u64 p02; MUL2(p02, xa0p, xa2p);
                FMA2(y2acc[k], p02, wV2, y2acc[k]);
                u64 p11; MUL2(p11, xa1p[a], xa1p[b]);
                FMA2(y2acc[k], p11, wV4, y2acc[k]);
                FMA2(y2acc[k], xrp, wV7, y2acc[k]);
            }
        }
    }

    float y0 = hadd2(y0acc);
    float y1[3], y2[9];
#pragma unroll
    for (int a = 0; a < 3; a++) y1[a] = hadd2(y1acc[a]);
#pragma unroll
    for (int k = 0; k < 9; k++) y2[k] = hadd2(y2acc[k]);

    // gates
    float* Ys = sY + warp * 32;
    Ys[d] = y0;
    __syncwarp();
    u64 gp0a = 0ull, gp1a = 0ull, gp2a = 0ull;
#pragma unroll 4
    for (int cp = 0; cp < 16; cp++) {
        u64 yp = *(const u64*)(Ys + cp * 2);
        int wb = cp * 32 + d;
        FMA2(gp0a, yp, wg64[0 * 512 + wb], gp0a);
        FMA2(gp1a, yp, wg64[1 * 512 + wb], gp1a);
        FMA2(gp2a, yp, wg64[2 * 512 + wb], gp2a);
    }
    float gp0 = hadd2(gp0a), gp1 = hadd2(gp1a), gp2 = hadd2(gp2a);
    float gate0 = gp0 / (1.0f + __expf(-gp0));
    float gate1 = gp1 / (1.0f + __expf(-gp1));
    float gate2 = gp2 / (1.0f + __expf(-gp2));

    float* out0 = out;
    float* out1 = out + (size_t)N * 32;
    float* out2 = out + (size_t)N * 32 * 4;

    out0[i0] = node0[i0] + gate0;
    float* o1p = out1 + (size_t)i0 * 3;
#pragma unroll
    for (int a = 0; a < 3; a++) o1p[a] = g_n1T[a][i0] + y1[a] * gate1;
    float* o2p = out2 + (size_t)i0 * 9;
#pragma unroll
    for (int k = 0; k < 9; k++) o2p[k] = g_n2T[k][i0] + y2[k] * gate2;
}

// ---------------------------------------------------------------------------
extern "C" void kernel_launch(void* const* d_in, const int* in_sizes, int n_in,
                              void* d_out, int out_size)
{
    const float* node0 = (const float*)d_in[0];
    const float* node1 = (const float*)d_in[1];
    const float* node2 = (const float*)d_in[2];
    const float* rij   = (const float*)d_in[3];
    const float* Wrad  = (const float*)d_in[4];
    const float* U     = (const float*)d_in[5];
    const float* V     = (const float*)d_in[6];
    const float* Wg    = (const float*)d_in[7];
    const int*   idx_i = (const int*)d_in[8];
    const int*   idx_j = (const int*)d_in[9];
    float* out = (float*)d_out;

    int N = in_sizes[0] / 32;
    int E = in_sizes[8];
    int NC = N * 32;
    int GMAX = (E > NC) ? E : NC;

    int node_smem = (11264 + 3072 + NWARPS * 27 * 32 + NWARPS * 32) * (int)sizeof(float);
    cudaFuncSetAttribute(node_kernel, cudaFuncAttributeMaxDynamicSharedMemorySize, node_smem);

    zero_deg_kernel<<<(N + 255) / 256, 256>>>(N);
    hist_transpose_kernel<<<(GMAX + 255) / 256, 256>>>(idx_i, node1, node2, E, NC);
    scan_kernel<<<1, 1024>>>(N, E);
    scatter_kernel<<<(E + 255) / 256, 256>>>(idx_i, E);
    edge_kernel<<<(N + 3) / 4, 128>>>(node0, rij, Wrad, idx_j, N);
    node_kernel<<<(N + NWARPS - 1) / NWARPS, 32 * NWARPS, node_smem>>>(
        node0, U, V, Wg, out, N);
}

// round 7
// speedup vs baseline: 1.2448x; 1.2448x over previous
#include <cuda_runtime.h>
#include <math.h>

typedef unsigned long long u64;

#define NMAX 20000
#define EMAX 320000
#define N32  (NMAX * 32)

// f32x2 packed helpers
#define FMA2(d, a, b, c) asm("fma.rn.f32x2 %0, %1, %2, %3;" : "=l"(d) : "l"(a), "l"(b), "l"(c))
#define MUL2(d, a, b)    asm("mul.rn.f32x2 %0, %1, %2;" : "=l"(d) : "l"(a), "l"(b))
#define PACK2(d, lo, hi) asm("mov.b64 %0, {%1, %2};" : "=l"(d) : "f"(lo), "f"(hi))
#define UNPACK2(lo, hi, s) asm("mov.b64 {%0, %1}, %2;" : "=f"(lo), "=f"(hi) : "l"(s))

__device__ __forceinline__ float hadd2(u64 v) {
    float lo, hi; UNPACK2(lo, hi, v); return lo + hi;
}

// CSR build scratch
__device__ int g_deg[NMAX];
__device__ int g_off[NMAX + 1];
__device__ int g_cur[NMAX];
__device__ int g_edge[EMAX];

// transposed node features (plane-major for coalesced gather)
__device__ float g_n1T[3][N32];
__device__ float g_n2T[9][N32];

// aggregated per-node accumulators (plane-major)
__device__ float g_A0[N32];
__device__ float g_A1[3][N32];
__device__ float g_A2[9][N32];

// ---------------------------------------------------------------------------
__global__ void zero_deg_kernel(int N) {
    int i = blockIdx.x * blockDim.x + threadIdx.x;
    if (i < N) g_deg[i] = 0;
}

// fused histogram + feature transpose
__global__ void hist_transpose_kernel(const int* __restrict__ idx_i,
                                      const float* __restrict__ node1,
                                      const float* __restrict__ node2,
                                      int E, int NC) {
    int i = blockIdx.x * blockDim.x + threadIdx.x;
    if (i < E) atomicAdd(&g_deg[idx_i[i]], 1);
    if (i < NC) {
#pragma unroll
        for (int a = 0; a < 3; a++) g_n1T[a][i] = node1[(size_t)i * 3 + a];
#pragma unroll
        for (int k = 0; k < 9; k++) g_n2T[k][i] = node2[(size_t)i * 9 + k];
    }
}

__global__ void scan_kernel(int N, int E) {
    __shared__ int ssum[1024];
    int t = threadIdx.x;
    int chunk = (N + 1023) / 1024;
    int base = t * chunk;
    int s = 0;
    for (int k = 0; k < chunk; k++) {
        int idx = base + k;
        if (idx < N) s += g_deg[idx];
    }
    ssum[t] = s;
    __syncthreads();
    for (int off = 1; off < 1024; off <<= 1) {
        int v = (t >= off) ? ssum[t - off] : 0;
        __syncthreads();
        ssum[t] += v;
        __syncthreads();
    }
    int run = ssum[t] - s;
    for (int k = 0; k < chunk; k++) {
        int idx = base + k;
        if (idx < N) {
            int d = g_deg[idx];
            g_off[idx] = run;
            g_cur[idx] = run;
            run += d;
        }
    }
    if (t == 0) g_off[N] = E;
}

__global__ void scatter_kernel(const int* __restrict__ idx_i, int E) {
    int e = blockIdx.x * blockDim.x + threadIdx.x;
    if (e < E) {
        int p = atomicAdd(&g_cur[idx_i[e]], 1);
        g_edge[p] = e;
    }
}

// ---------------------------------------------------------------------------
// Edge aggregation: persistent warps, grid-stride over nodes; lane = channel.
// Wrad pre-packed ONCE per warp into 44 basis-pair f32x2 registers.
// Inner loop identical to the proven R4 version.
// ---------------------------------------------------------------------------
__global__ __launch_bounds__(128, 3)
void edge_kernel(const float* __restrict__ node0,
                 const float* __restrict__ rij,
                 const float* __restrict__ Wrad,
                 const int* __restrict__ idx_j,
                 int N)
{
    int warp = threadIdx.x >> 5;
    int lane = threadIdx.x & 31;
    int gwarp = blockIdx.x * 4 + warp;
    int nwt = gridDim.x * 4;

    // Wrad[p][b][lane], packed over basis pairs (done ONCE per warp)
    u64 Wreg2[44];
#pragma unroll
    for (int p = 0; p < 11; p++)
#pragma unroll
        for (int i = 0; i < 4; i++) {
            float lo = Wrad[(p * 8 + 2 * i) * 32 + lane];
            float hi = Wrad[(p * 8 + 2 * i + 1) * 32 + lane];
            PACK2(Wreg2[p * 4 + i], lo, hi);
        }

    for (int n = gwarp; n < N; n += nwt) {
        float A0 = 0.0f;
        float A1[3] = {0.0f, 0.0f, 0.0f};
        float A2[9] = {0.0f, 0.0f, 0.0f, 0.0f, 0.0f, 0.0f, 0.0f, 0.0f, 0.0f};

        int beg = g_off[n];
        int end = g_off[n + 1];

        for (int k0 = beg; k0 < end; k0 += 32) {
            int cnt = min(32, end - k0);
            int pos = k0 + lane;
            int eL = g_edge[(pos < end) ? pos : (end - 1)];
            int jL = idx_j[eL];

            int e0 = __shfl_sync(0xffffffffu, eL, 0);
            float nrx = rij[3 * e0 + 0];
            float nry = rij[3 * e0 + 1];
            float nrz = rij[3 * e0 + 2];

            for (int kk = 0; kk < cnt; kk++) {
                int j = __shfl_sync(0xffffffffu, jL, kk);
                int jc = j * 32 + lane;

                // issue gathers early
                float g0 = node0[jc];
                float g1v[3];
#pragma unroll
                for (int a = 0; a < 3; a++) g1v[a] = g_n1T[a][jc];
                float g2[9];
#pragma unroll
                for (int k = 0; k < 9; k++) g2[k] = g_n2T[k][jc];

                float rx = nrx, ry = nry, rz = nrz;
                if (kk + 1 < cnt) {
                    int e1 = __shfl_sync(0xffffffffu, eL, kk + 1);
                    nrx = rij[3 * e1 + 0];
                    nry = rij[3 * e1 + 1];
                    nrz = rij[3 * e1 + 2];
                }

                float dd = rx * rx + ry * ry + rz * rz + 1e-12f;
                float inv = rsqrtf(dd);
                float dist = dd * inv;
                float h0 = rx * inv, h1 = ry * inv, h2 = rz * inv;

                float uu = fminf(dist * 0.2f, 1.0f);
                float fc = 0.5f * (__cosf(3.14159265358979323846f * uu) + 1.0f);

                // basis values, packed over pairs
                u64 rb2[4];
#pragma unroll
                for (int i = 0; i < 4; i++) {
                    float c0v = 0.5f + (float)(2 * i) * (4.5f / 7.0f);
                    float c1v = 0.5f + (float)(2 * i + 1) * (4.5f / 7.0f);
                    float d0 = dist - c0v, d1l = dist - c1v;
                    float r0 = __expf(-4.0f * d0 * d0) * fc;
                    float r1 = __expf(-4.0f * d1l * d1l) * fc;
                    PACK2(rb2[i], r0, r1);
                }

                // w[p] = sum_b rb[b] * W[p,b]
                float w[11];
#pragma unroll
                for (int p = 0; p < 11; p++) {
                    u64 acc = 0ull;
#pragma unroll
                    for (int i = 0; i < 4; i++) FMA2(acc, rb2[i], Wreg2[p * 4 + i], acc);
                    w[p] = hadd2(acc);
                }

                float hh[3] = {h0, h1, h2};
                float d1 = g1v[0] * h0 + g1v[1] * h1 + g1v[2] * h2;
                float d2[3];
#pragma unroll
                for (int a = 0; a < 3; a++)
                    d2[a] = g2[a * 3 + 0] * h0 + g2[a * 3 + 1] * h1 + g2[a * 3 + 2] * h2;
                float q = d2[0] * h0 + d2[1] * h1 + d2[2] * h2;

                A0 += g0 * w[0] + d1 * w[4] + q * w[9];

                float s01 = g0 * w[1] + d1 * w[6];
#pragma unroll
                for (int a = 0; a < 3; a++)
                    A1[a] += s01 * hh[a] + g1v[a] * w[3] + d2[a] * w[8];

                float gw2 = g0 * w[2];
#pragma unroll
                for (int a = 0; a < 3; a++) {
                    float pre = gw2 * hh[a] + g1v[a] * w[5] + d2[a] * w[10];
#pragma unroll
                    for (int b = 0; b < 3; b++)
                        A2[a * 3 + b] += pre * hh[b] + g2[a * 3 + b] * w[7];
                }
            }
        }

        const float norm = 1.0f / 16.0f;
        int i0 = n * 32 + lane;
        g_A0[i0] = A0 * norm;
#pragma unroll
        for (int a = 0; a < 3; a++) g_A1[a][i0] = A1[a] * norm;
#pragma unroll
        for (int k = 0; k < 9; k++) g_A2[k][i0] = A2[k] * norm;
    }
}

// ---------------------------------------------------------------------------
// Node kernel: persistent blocks, grid-stride over nodes; warp per node.
// Weights staged + pair-interleaved ONCE per block; c-loop in f32x2.
// ---------------------------------------------------------------------------
#define NWARPS 8

__global__ __launch_bounds__(256, 2)
void node_kernel(const float* __restrict__ node0,
                 const float* __restrict__ U,
                 const float* __restrict__ V,
                 const float* __restrict__ Wg,
                 float* __restrict__ out,
                 int N)
{
    extern __shared__ float sh[];
    float* sWm = sh;                           // 11*1024 paired
    float* sWg = sWm + 11264;                  // 3*1024 paired
    float* sX  = sWg + 3072;                   // NWARPS * 27 * 32
    float* sY  = sX + NWARPS * 27 * 32;        // NWARPS * 32

    for (int i = threadIdx.x; i < 11 * 1024; i += blockDim.x) {
        float v = (i < 3 * 1024) ? U[i] : V[i - 3 * 1024];
        int m = i >> 10, c = (i >> 5) & 31, d = i & 31;
        sWm[(m << 10) + ((c >> 1) << 6) + (d << 1) + (c & 1)] = v;
    }
    for (int i = threadIdx.x; i < 3 * 1024; i += blockDim.x) {
        int m = i >> 10, c = (i >> 5) & 31, d = i & 31;
        sWg[(m << 10) + ((c >> 1) << 6) + (d << 1) + (c & 1)] = Wg[i];
    }
    __syncthreads();

    int warp = threadIdx.x >> 5;
    int lane = threadIdx.x & 31;
    int gwarp = blockIdx.x * NWARPS + warp;
    int nwt = gridDim.x * NWARPS;

    int d = lane;
    const u64* wm64 = (const u64*)sWm;         // idx: m*512 + cp*32 + d
    const u64* wg64 = (const u64*)sWg;
    float* Xs = sX + warp * 27 * 32;
    float* Ys = sY + warp * 32;

    for (int n = gwarp; n < N; n += nwt) {
        int i0 = n * 32 + lane;
        float a0 = g_A0[i0];
        float a1[3];
#pragma unroll
        for (int a = 0; a < 3; a++) a1[a] = g_A1[a][i0];
        float a2[9];
#pragma unroll
        for (int k = 0; k < 9; k++) a2[k] = g_A2[k][i0];

        float s1 = a1[0] * a1[0] + a1[1] * a1[1] + a1[2] * a1[2];
        float s2 = 0.0f;
#pragma unroll
        for (int k = 0; k < 9; k++) s2 += a2[k] * a2[k];
        float t[3];
#pragma unroll
        for (int b = 0; b < 3; b++)
            t[b] = a1[0] * a2[0 * 3 + b] + a1[1] * a2[1 * 3 + b] + a1[2] * a2[2 * 3 + b];
        float r[9];
#pragma unroll
        for (int a = 0; a < 3; a++)
#pragma unroll
            for (int b = 0; b < 3; b++)
                r[a * 3 + b] = a2[a * 3 + 0] * a2[0 * 3 + b]
                             + a2[a * 3 + 1] * a2[1 * 3 + b]
                             + a2[a * 3 + 2] * a2[2 * 3 + b];

        Xs[0 * 32 + lane] = a0;
        Xs[1 * 32 + lane] = s1;
        Xs[2 * 32 + lane] = s2;
#pragma unroll
        for (int a = 0; a < 3; a++) { Xs[(3 + a) * 32 + lane] = a1[a]; Xs[(6 + a) * 32 + lane] = t[a]; }
#pragma unroll
        for (int k = 0; k < 9; k++) { Xs[(9 + k) * 32 + lane] = a2[k]; Xs[(18 + k) * 32 + lane] = r[k]; }
        __syncwarp();

        u64 y0acc = 0ull;
        u64 y1acc[3] = {0ull, 0ull, 0ull};
        u64 y2acc[9] = {0ull, 0ull, 0ull, 0ull, 0ull, 0ull, 0ull, 0ull, 0ull};

#pragma unroll 2
        for (int cp = 0; cp < 16; cp++) {
            int c = cp * 2;
            int wb = cp * 32 + d;

            u64 xa0p = *(const u64*)(Xs + 0 * 32 + c);
            u64 xs1p = *(const u64*)(Xs + 1 * 32 + c);
            u64 xs2p = *(const u64*)(Xs + 2 * 32 + c);

            FMA2(y0acc, xa0p, wm64[0 * 512 + wb], y0acc);
            u64 xa0sq; MUL2(xa0sq, xa0p, xa0p);
            FMA2(y0acc, xa0sq, wm64[3 * 512 + wb], y0acc);
            FMA2(y0acc, xs1p, wm64[6 * 512 + wb], y0acc);
            FMA2(y0acc, xs2p, wm64[9 * 512 + wb], y0acc);

            u64 wU1 = wm64[1 * 512 + wb];
            u64 wV1 = wm64[4 * 512 + wb];
            u64 wV5 = wm64[8 * 512 + wb];
            u64 xa1p[3];
#pragma unroll
            for (int a = 0; a < 3; a++) {
                xa1p[a] = *(const u64*)(Xs + (3 + a) * 32 + c);
                u64 xtp = *(const u64*)(Xs + (6 + a) * 32 + c);
                FMA2(y1acc[a], xa1p[a], wU1, y1acc[a]);
                u64 p01; MUL2(p01, xa0p, xa1p[a]);
                FMA2(y1acc[a], p01, wV1, y1acc[a]);
                FMA2(y1acc[a], xtp, wV5, y1acc[a]);
            }

            u64 wU2 = wm64[2 * 512 + wb];
            u64 wV2 = wm64[5 * 512 + wb];
            u64 wV4 = wm64[7 * 512 + wb];
            u64 wV7 = wm64[10 * 512 + wb];
#pragma unroll
            for (int a = 0; a < 3; a++) {
#pragma unroll
                for (int b = 0; b < 3; b++) {
                    int k = a * 3 + b;
                    u64 xa2p = *(const u64*)(Xs + (9 + k) * 32 + c);
                    u64 xrp  = *(const u64*)(Xs + (18 + k) * 32 + c);
                    FMA2(y2acc[k], xa2p, wU2, y2acc[k]);
                    u64 p02; MUL2(p02, xa0p, xa2p);
                    FMA2(y2acc[k], p02, wV2, y2acc[k]);
                    u64 p11; MUL2(p11, xa1p[a], xa1p[b]);
                    FMA2(y2acc[k], p11, wV4, y2acc[k]);
                    FMA2(y2acc[k], xrp, wV7, y2acc[k]);
                }
            }
        }

        float y0 = hadd2(y0acc);
        float y1[3], y2[9];
#pragma unroll
        for (int a = 0; a < 3; a++) y1[a] = hadd2(y1acc[a]);
#pragma unroll
        for (int k = 0; k < 9; k++) y2[k] = hadd2(y2acc[k]);

        // gates
        Ys[d] = y0;
        __syncwarp();
        u64 gp0a = 0ull, gp1a = 0ull, gp2a = 0ull;
#pragma unroll 4
        for (int cp = 0; cp < 16; cp++) {
            u64 yp = *(const u64*)(Ys + cp * 2);
            int wb = cp * 32 + d;
            FMA2(gp0a, yp, wg64[0 * 512 + wb], gp0a);
            FMA2(gp1a, yp, wg64[1 * 512 + wb], gp1a);
            FMA2(gp2a, yp, wg64[2 * 512 + wb], gp2a);
        }
        float gp0 = hadd2(gp0a), gp1 = hadd2(gp1a), gp2 = hadd2(gp2a);
        float gate0 = gp0 / (1.0f + __expf(-gp0));
        float gate1 = gp1 / (1.0f + __expf(-gp1));
        float gate2 = gp2 / (1.0f + __expf(-gp2));

        float* out0 = out;
        float* out1 = out + (size_t)N * 32;
        float* out2 = out + (size_t)N * 32 * 4;

        out0[i0] = node0[i0] + gate0;
        float* o1p = out1 + (size_t)i0 * 3;
#pragma unroll
        for (int a = 0; a < 3; a++) o1p[a] = g_n1T[a][i0] + y1[a] * gate1;
        float* o2p = out2 + (size_t)i0 * 9;
#pragma unroll
        for (int k = 0; k < 9; k++) o2p[k] = g_n2T[k][i0] + y2[k] * gate2;
        __syncwarp();
    }
}

// ---------------------------------------------------------------------------
extern "C" void kernel_launch(void* const* d_in, const int* in_sizes, int n_in,
                              void* d_out, int out_size)
{
    const float* node0 = (const float*)d_in[0];
    const float* node1 = (const float*)d_in[1];
    const float* node2 = (const float*)d_in[2];
    const float* rij   = (const float*)d_in[3];
    const float* Wrad  = (const float*)d_in[4];
    const float* U     = (const float*)d_in[5];
    const float* V     = (const float*)d_in[6];
    const float* Wg    = (const float*)d_in[7];
    const int*   idx_i = (const int*)d_in[8];
    const int*   idx_j = (const int*)d_in[9];
    float* out = (float*)d_out;

    int N = in_sizes[0] / 32;
    int E = in_sizes[8];
    int NC = N * 32;
    int GMAX = (E > NC) ? E : NC;

    int node_smem = (11264 + 3072 + NWARPS * 27 * 32 + NWARPS * 32) * (int)sizeof(float);
    cudaFuncSetAttribute(node_kernel, cudaFuncAttributeMaxDynamicSharedMemorySize, node_smem);

    zero_deg_kernel<<<(N + 255) / 256, 256>>>(N);
    hist_transpose_kernel<<<(GMAX + 255) / 256, 256>>>(idx_i, node1, node2, E, NC);
    scan_kernel<<<1, 1024>>>(N, E);
    scatter_kernel<<<(E + 255) / 256, 256>>>(idx_i, E);
    edge_kernel<<<444, 128>>>(node0, rij, Wrad, idx_j, N);
    node_kernel<<<296, 256, node_smem>>>(node0, U, V, Wg, out, N);
}